// round 12
// baseline (speedup 1.0000x reference)
#include <cuda_runtime.h>
#include <cstdint>

// Inverse 3D Haar synthesis:
//   in  : [B=2, 8*16, T=8, H=128, W=128] fp32 (8 subbands of 16 channels)
//   out : [B=2, 16, 16, 256, 256] fp32
// out[b,g,2t+pt,2h+ph,2w+pw] = (1/8) * sum_s (-1)^(bt*pt+bh*ph+bw*pw) * x[b, s*16+g, t, h, w]
// with s = 4*bt + 2*bh + bw.
//
// CTA tile: 4 input h rows x full W for one (b,g,t). Butterfly into smem as
// two 8KB CONTIGUOUS output chunks (pt=0/1: 8 output rows x 1KB each), then
// 2x cp.async.bulk (TMA) smem->gmem stores. Writes hit DRAM as 8KB sequential
// bursts (better row locality, fewer r/w turnarounds) and bypass the LSU/L1
// store path entirely, freeing it for the read stream.

__device__ __forceinline__ float2 f2add(float2 a, float2 b) {
    return make_float2(a.x + b.x, a.y + b.y);
}
__device__ __forceinline__ float2 f2sub(float2 a, float2 b) {
    return make_float2(a.x - b.x, a.y - b.y);
}

__global__ __launch_bounds__(256) void ihaar3d_kernel(const float* __restrict__ x,
                                                      float* __restrict__ out) {
    // [pt][output row within chunk][256 floats] -> 2 x 8KB contiguous chunks.
    __shared__ __align__(16) float sbuf[2][8][256];

    const int tid = threadIdx.x;
    const int w2 = tid & 63;   // which w-pair within the row (w0 = 2*w2)
    const int hr = tid >> 6;   // which of the 4 input h rows (0..3)

    // CTA decode: [b(1)][g(4)][t(3)][h4(5)] -> 8192 CTAs.
    const int cta = blockIdx.x;
    const int h4 = cta & 31;
    const int t  = (cta >> 5) & 7;
    const int g  = (cta >> 8) & 15;
    const int b  = (cta >> 12) & 1;

    const int h  = h4 * 4 + hr;
    const int w0 = w2 << 1;

    // input: [B, 128, 8, 128, 128]; subband stride = 16 channels. Offsets fit int32.
    const int SUB = 16 * 8 * 128 * 128;  // 2,097,152
    const int base = (((b * 128 + g) * 8 + t) * 128 + h) * 128 + w0;

    float2 v0 = *reinterpret_cast<const float2*>(x + base + 0 * SUB);  // lll
    float2 v1 = *reinterpret_cast<const float2*>(x + base + 1 * SUB);  // llh
    float2 v2 = *reinterpret_cast<const float2*>(x + base + 2 * SUB);  // lhl
    float2 v3 = *reinterpret_cast<const float2*>(x + base + 3 * SUB);  // lhh
    float2 v4 = *reinterpret_cast<const float2*>(x + base + 4 * SUB);  // hll
    float2 v5 = *reinterpret_cast<const float2*>(x + base + 5 * SUB);  // hlh
    float2 v6 = *reinterpret_cast<const float2*>(x + base + 6 * SUB);  // hhl
    float2 v7 = *reinterpret_cast<const float2*>(x + base + 7 * SUB);  // hhh

    // Stage 1: W butterfly (bit0).
    float2 ll_e = f2add(v0, v1), ll_o = f2sub(v0, v1);
    float2 lh_e = f2add(v2, v3), lh_o = f2sub(v2, v3);
    float2 hl_e = f2add(v4, v5), hl_o = f2sub(v4, v5);
    float2 hh_e = f2add(v6, v7), hh_o = f2sub(v6, v7);

    // Stage 2: H butterfly (bit1): index = ph.
    float2 le[2] = {f2add(ll_e, lh_e), f2sub(ll_e, lh_e)};
    float2 lo[2] = {f2add(ll_o, lh_o), f2sub(ll_o, lh_o)};
    float2 he[2] = {f2add(hl_e, hh_e), f2sub(hl_e, hh_e)};
    float2 ho[2] = {f2add(hl_o, hh_o), f2sub(hl_o, hh_o)};

    // Stage 3: T butterfly (bit2) + scale into smem chunks.
    const float k = 0.125f;
#pragma unroll
    for (int pt = 0; pt < 2; ++pt) {
#pragma unroll
        for (int ph = 0; ph < 2; ++ph) {
            float2 e = pt == 0 ? f2add(le[ph], he[ph]) : f2sub(le[ph], he[ph]);
            float2 o = pt == 0 ? f2add(lo[ph], ho[ph]) : f2sub(lo[ph], ho[ph]);
            // chunk row = 2*hr + ph, columns 4*w2 .. 4*w2+3 (float4 aligned)
            *reinterpret_cast<float4*>(&sbuf[pt][2 * hr + ph][4 * w2]) =
                make_float4(e.x * k, o.x * k, e.y * k, o.y * k);
        }
    }

    __syncthreads();
    // Order generic-proxy smem writes before async-proxy (TMA) reads.
    asm volatile("fence.proxy.async.shared::cta;" ::: "memory");

    if (tid == 0) {
        // Output chunk pt: out[((b*16+g)*16 + 2t+pt)*65536 + 8*h4*256], 8KB.
        const int obase = (((b * 16 + g) * 16 + 2 * t) * 256 + 8 * h4) * 256;
        uint32_t s0, s1;
        asm("{ .reg .u64 a; cvta.to.shared.u64 a, %1; cvt.u32.u64 %0, a; }"
            : "=r"(s0) : "l"(&sbuf[0][0][0]));
        asm("{ .reg .u64 a; cvta.to.shared.u64 a, %1; cvt.u32.u64 %0, a; }"
            : "=r"(s1) : "l"(&sbuf[1][0][0]));
        asm volatile("cp.async.bulk.global.shared::cta.bulk_group [%0], [%1], %2;"
                     :: "l"(out + obase), "r"(s0), "r"(8192) : "memory");
        asm volatile("cp.async.bulk.global.shared::cta.bulk_group [%0], [%1], %2;"
                     :: "l"(out + obase + 65536), "r"(s1), "r"(8192) : "memory");
        asm volatile("cp.async.bulk.commit_group;" ::: "memory");
        asm volatile("cp.async.bulk.wait_group 0;" ::: "memory");
    }
}

extern "C" void kernel_launch(void* const* d_in, const int* in_sizes, int n_in,
                              void* d_out, int out_size) {
    const float* x = (const float*)d_in[0];
    float* out = (float*)d_out;
    // 8192 CTAs x 256 threads; each CTA: 4 input rows -> two 8KB output chunks.
    ihaar3d_kernel<<<8192, 256>>>(x, out);
}